// round 12
// baseline (speedup 1.0000x reference)
#include <cuda_runtime.h>
#include <cstdint>

#define B_   32
#define T_   512
#define E2   512
#define H_   1024
#define G_   4096
#define BT   16384
#define N0   2048
#define N1   512
#define NCTA 128

// chunked h layout: per step, 32 chunks of [32 rows][36 words]
#define ROWW    36
#define CH_W    (32 * ROWW)        // 1152 words per chunk
#define NCH     (H_ / 32)
#define HSTEP   (NCH * CH_W)       // 36864 words per step

#define DEC_NB0   (N0 / 64)        // 32
#define DEC_NB1   (N1 / 64)        // 8
#define DEC_NBT   (DEC_NB0 + DEC_NB1)   // 40 n-tiles per m-block
#define DEC_TILES (128 * DEC_NBT)       // 5120

// ------------------------- scratch (device globals, no allocs) -----------
__device__ __align__(256) uint32_t g_x[(size_t)BT * E2];
__device__ __align__(256) float    g_xproj[(size_t)BT * G_];
__device__ __align__(256) uint32_t g_hstf[(size_t)(T_ + 1) * HSTEP];
__device__ __align__(256) uint32_t g_wih_tf[(size_t)G_ * E2];
__device__ __align__(256) uint32_t g_whh_tf[(size_t)G_ * H_];
__device__ __align__(256) uint32_t g_wd0_tf[(size_t)N0 * H_];
__device__ __align__(256) uint32_t g_wd1_tf[(size_t)N1 * H_];
__device__ unsigned g_gcnt[8 * 64];      // 8 group counters, 256B apart
__device__ unsigned g_ticket;            // decoder tile work queue

// ------------------------- helpers ---------------------------------------
__device__ __forceinline__ uint32_t f2tf(float f) {
    uint32_t u;
    asm("cvt.rna.tf32.f32 %0, %1;" : "=r"(u) : "f"(f));
    return u;
}

__device__ __forceinline__ void mma_tf32(float& c0, float& c1, float& c2, float& c3,
                                         uint32_t a0, uint32_t a1, uint32_t a2, uint32_t a3,
                                         uint32_t b0, uint32_t b1) {
    asm volatile(
        "mma.sync.aligned.m16n8k8.row.col.f32.tf32.tf32.f32 "
        "{%0,%1,%2,%3},{%4,%5,%6,%7},{%8,%9},{%0,%1,%2,%3};"
        : "+f"(c0), "+f"(c1), "+f"(c2), "+f"(c3)
        : "r"(a0), "r"(a1), "r"(a2), "r"(a3), "r"(b0), "r"(b1));
}

__device__ __forceinline__ void ldsm4(uint32_t& r0, uint32_t& r1, uint32_t& r2, uint32_t& r3,
                                      uint32_t saddr) {
    asm volatile("ldmatrix.sync.aligned.m8n8.x4.shared.b16 {%0,%1,%2,%3}, [%4];"
                 : "=r"(r0), "=r"(r1), "=r"(r2), "=r"(r3) : "r"(saddr));
}

__device__ __forceinline__ void cp16(uint32_t sdst, const void* gsrc) {
    asm volatile("cp.async.cg.shared.global [%0], [%1], 16;" :: "r"(sdst), "l"(gsrc) : "memory");
}

__device__ __forceinline__ void bulkcp(uint32_t sdst, const void* gsrc, uint32_t bytes,
                                       uint32_t mbar) {
    asm volatile(
        "cp.async.bulk.shared::cta.global.mbarrier::complete_tx::bytes [%0], [%1], %2, [%3];"
        :: "r"(sdst), "l"(gsrc), "r"(bytes), "r"(mbar) : "memory");
}

__device__ __forceinline__ void mb_init(uint32_t mbar, uint32_t cnt) {
    asm volatile("mbarrier.init.shared.b64 [%0], %1;" :: "r"(mbar), "r"(cnt) : "memory");
}

__device__ __forceinline__ void mb_expect(uint32_t mbar, uint32_t bytes) {
    asm volatile("mbarrier.arrive.expect_tx.shared.b64 _, [%0], %1;"
                 :: "r"(mbar), "r"(bytes) : "memory");
}

__device__ __forceinline__ void mb_wait(uint32_t mbar, uint32_t parity) {
    asm volatile(
        "{\n\t.reg .pred P;\n\t"
        "MBW_%=:\n\t"
        "mbarrier.try_wait.parity.acquire.cta.shared::cta.b64 P, [%0], %1, 0x989680;\n\t"
        "@P bra.uni MBD_%=;\n\t"
        "bra.uni MBW_%=;\n\t"
        "MBD_%=:\n\t}"
        :: "r"(mbar), "r"(parity) : "memory");
}

__device__ __forceinline__ unsigned ld_acq(const unsigned* p) {
    unsigned v;
    asm volatile("ld.acquire.gpu.u32 %0, [%1];" : "=r"(v) : "l"(p));
    return v;
}

__device__ __forceinline__ void red_release(unsigned* p, unsigned v) {
    asm volatile("red.release.gpu.global.add.u32 [%0], %1;" :: "l"(p), "r"(v) : "memory");
}

__device__ __forceinline__ float fsig(float x) {
    return __fdividef(1.f, 1.f + __expf(-x));
}
__device__ __forceinline__ float ftanh(float x) {
    return 1.f - __fdividef(2.f, __expf(2.f * x) + 1.f);
}

// ------------------------- prep ------------------------------------------
__global__ void prep_kernel(const float* __restrict__ W_ih, const float* __restrict__ W_hh,
                            const float* __restrict__ Wd0, const float* __restrict__ Wd1,
                            const float* __restrict__ h0) {
    size_t i = (size_t)blockIdx.x * blockDim.x + threadIdx.x;
    size_t stride = (size_t)gridDim.x * blockDim.x;
    for (size_t k = i; k < (size_t)G_ * H_; k += stride) g_whh_tf[k] = f2tf(W_hh[k]);
    for (size_t k = i; k < (size_t)G_ * E2; k += stride) g_wih_tf[k] = f2tf(W_ih[k]);
    for (size_t k = i; k < (size_t)N0 * H_; k += stride) g_wd0_tf[k] = f2tf(Wd0[k]);
    for (size_t k = i; k < (size_t)N1 * H_; k += stride) g_wd1_tf[k] = f2tf(Wd1[k]);
    if (i < (size_t)B_ * H_) {
        int b = (int)(i >> 10), k = (int)(i & 1023);
        g_hstf[(size_t)(k >> 5) * CH_W + b * ROWW + (k & 31)] = f2tf(h0[i]);
    }
    if (i < 8 * 64) g_gcnt[i] = 0;
    if (i == 0) g_ticket = 0;
}

// ------------------------- pack ------------------------------------------
__global__ void pack_kernel(const int* __restrict__ tok0, const int* __restrict__ tok1,
                            const float* __restrict__ emb0, const float* __restrict__ emb1) {
    int row = blockIdx.x;
    int t = row >> 5, b = row & 31;
    int tid = threadIdx.x;
    uint4* dst = reinterpret_cast<uint4*>(g_x + (size_t)row * E2);
    float4 v;
    if (tid < 64) {
        int tk = tok0[b * T_ + t];
        v = reinterpret_cast<const float4*>(emb0 + (size_t)tk * 256)[tid];
    } else {
        int tk = tok1[b * T_ + t];
        v = reinterpret_cast<const float4*>(emb1 + (size_t)tk * 256)[tid - 64];
    }
    dst[tid] = make_uint4(f2tf(v.x), f2tf(v.y), f2tf(v.z), f2tf(v.w));
}

// ------------------------- GEMM tile body (v2, R7-proven) ----------------
// BM=128, BN=64, BK=32, 256 thr, register-staged double buffer + ldmatrix.
// A in g_hstf chunked layout if AHSCHUNK; REMAP maps row t*32+b -> b*512+t.
#define GEMM_SMEM_BYTES ((2 * 128 * 36 + 2 * 64 * 36) * 4)   // 55296

template <bool REMAP, bool AHSCHUNK>
__device__ __forceinline__ void gemm_tile(
    uint32_t* smem, const uint32_t* __restrict__ A, const uint32_t* __restrict__ Bm,
    const float* __restrict__ bias1, const float* __restrict__ bias2,
    float* __restrict__ C, int N, int K, int bm, int bn) {
    uint32_t* sA = smem;
    uint32_t* sB = smem + 2 * 128 * 36;
    const int tid = threadIdx.x;
    const int lane = tid & 31, warp = tid >> 5;
    const int wm = (warp >> 1) * 32;
    const int wn = (warp & 1) * 32;
    const int grp = lane >> 2, tig = lane & 3;
    const int KT = K >> 5;
    const uint32_t smem_b = (uint32_t)__cvta_generic_to_shared(smem);

    uint4 ra[4], rb[2];
    auto gload = [&](int kb) {
#pragma unroll
        for (int i = 0; i < 4; i++) {
            int lin = tid + i * 256;
            int r = lin >> 3, c4 = lin & 7;
            if (AHSCHUNK) {
                int row = bm + r;
                int t = row >> 5, bb = row & 31;
                ra[i] = *reinterpret_cast<const uint4*>(
                    A + (size_t)t * HSTEP + (size_t)kb * CH_W + bb * ROWW + c4 * 4);
            } else {
                ra[i] = reinterpret_cast<const uint4*>(A + (size_t)(bm + r) * K + kb * 32)[c4];
            }
        }
#pragma unroll
        for (int i = 0; i < 2; i++) {
            int lin = tid + i * 256;
            int r = lin >> 3, c4 = lin & 7;
            rb[i] = reinterpret_cast<const uint4*>(Bm + (size_t)(bn + r) * K + kb * 32)[c4];
        }
    };
    auto sstore = [&](int buf) {
        uint32_t* a = sA + buf * 128 * 36;
        uint32_t* b = sB + buf * 64 * 36;
#pragma unroll
        for (int i = 0; i < 4; i++) {
            int lin = tid + i * 256;
            int r = lin >> 3, c4 = lin & 7;
            *reinterpret_cast<uint4*>(a + r * 36 + c4 * 4) = ra[i];
        }
#pragma unroll
        for (int i = 0; i < 2; i++) {
            int lin = tid + i * 256;
            int r = lin >> 3, c4 = lin & 7;
            *reinterpret_cast<uint4*>(b + r * 36 + c4 * 4) = rb[i];
        }
    };

    float acc[2][4][4];
#pragma unroll
    for (int i = 0; i < 2; i++)
#pragma unroll
        for (int j = 0; j < 4; j++)
#pragma unroll
            for (int r = 0; r < 4; r++) acc[i][j][r] = 0.f;

    gload(0);
    sstore(0);
    __syncthreads();

    const int arow = ((lane >> 3) & 1) * 8 + (lane & 7);
    const int ahi = (lane >> 4) * 4;

    for (int kb = 0; kb < KT; kb++) {
        if (kb + 1 < KT) gload(kb + 1);
        const uint32_t aoff = (uint32_t)((kb & 1) * 128 * 36) * 4;
        const uint32_t boff = (uint32_t)(2 * 128 * 36 + (kb & 1) * 64 * 36) * 4;
#pragma unroll
        for (int kp = 0; kp < 2; kp++) {
            uint32_t bfr[4][4];
#pragma unroll
            for (int j = 0; j < 4; j++) {
                int n = wn + j * 8 + (lane & 7);
                int col = kp * 16 + (lane >> 3) * 4;
                ldsm4(bfr[j][0], bfr[j][1], bfr[j][2], bfr[j][3],
                      smem_b + boff + (uint32_t)(n * 36 + col) * 4);
            }
#pragma unroll
            for (int k2 = 0; k2 < 2; k2++) {
                int kt = kp * 2 + k2;
                uint32_t afr[2][4];
#pragma unroll
                for (int i = 0; i < 2; i++) {
                    int row = wm + i * 16 + arow;
                    ldsm4(afr[i][0], afr[i][1], afr[i][2], afr[i][3],
                          smem_b + aoff + (uint32_t)(row * 36 + kt * 8 + ahi) * 4);
                }
#pragma unroll
                for (int i = 0; i < 2; i++)
#pragma unroll
                    for (int j = 0; j < 4; j++)
                        mma_tf32(acc[i][j][0], acc[i][j][1], acc[i][j][2], acc[i][j][3],
                                 afr[i][0], afr[i][1], afr[i][2], afr[i][3],
                                 bfr[j][k2 * 2], bfr[j][k2 * 2 + 1]);
            }
        }
        if (kb + 1 < KT) {
            __syncthreads();
            sstore((kb + 1) & 1);
            __syncthreads();
        }
    }

#pragma unroll
    for (int i = 0; i < 2; i++) {
#pragma unroll
        for (int j = 0; j < 4; j++) {
            int col = bn + wn + j * 8 + tig * 2;
            float bv0 = 0.f, bv1 = 0.f;
            if (bias1) { bv0 = bias1[col]; bv1 = bias1[col + 1]; }
            if (bias2) { bv0 += bias2[col]; bv1 += bias2[col + 1]; }
            int r0 = bm + wm + i * 16 + grp;
            int r1 = r0 + 8;
            int or0 = REMAP ? ((r0 & 31) * T_ + (r0 >> 5)) : r0;
            int or1 = REMAP ? ((r1 & 31) * T_ + (r1 >> 5)) : r1;
            *reinterpret_cast<float2*>(C + (size_t)or0 * N + col) =
                make_float2(acc[i][j][0] + bv0, acc[i][j][1] + bv1);
            *reinterpret_cast<float2*>(C + (size_t)or1 * N + col) =
                make_float2(acc[i][j][2] + bv0, acc[i][j][3] + bv1);
        }
    }
}

// xproj GEMM (standalone grid kernel)
__launch_bounds__(256, 2)
__global__ void gemm_xproj_kernel(const uint32_t* __restrict__ A, const uint32_t* __restrict__ Bm,
                                  const float* __restrict__ bias1, const float* __restrict__ bias2,
                                  float* __restrict__ C, int N, int K) {
    extern __shared__ uint32_t smem[];
    gemm_tile<false, false>(smem, A, Bm, bias1, bias2, C, N, K,
                            blockIdx.y * 128, blockIdx.x * 64);
}

// ------------------------- decoder: ticket-queue GEMM --------------------
// WAIT=true: persistent worker that claims a tile ONLY when the recurrence
// counters show its time-block complete (CAS-claim, cannot strand a ticket).
// Bounded idle-timeout exits gracefully if the recurrence isn't concurrent.
// WAIT=false: post-recurrence finisher, unconditional atomicAdd claims.
template <bool WAIT>
__launch_bounds__(256, 2)
__global__ void dec_kernel(const uint32_t* __restrict__ hsA,
                           const uint32_t* __restrict__ wd0, const uint32_t* __restrict__ wd1,
                           const float* __restrict__ bd0, const float* __restrict__ bd1,
                           float* __restrict__ out) {
    extern __shared__ uint32_t smem[];
    __shared__ unsigned s_tk;
    const int tid = threadIdx.x;

    for (;;) {
        if (tid == 0) {
            unsigned got = 0xFFFFFFFFu;
            if (WAIT) {
                int idle = 0;
                for (;;) {
                    unsigned cur = *((volatile unsigned*)&g_ticket);
                    if (cur >= DEC_TILES) break;
                    unsigned prog = 0xFFFFFFFFu;
#pragma unroll
                    for (int g = 0; g < 8; g++) prog = umin(prog, ld_acq(&g_gcnt[g * 64]));
                    unsigned avail = (prog >> 6) * DEC_NBT;   // (prog/64) m-blocks ready
                    if (cur < avail) {
                        if (atomicCAS(&g_ticket, cur, cur + 1) == cur) { got = cur; break; }
                        continue;
                    }
                    if (++idle > 20000) break;   // ~5 ms safety: finisher takes the rest
                    __nanosleep(256);
                }
            } else {
                unsigned cur = atomicAdd(&g_ticket, 1u);
                if (cur < DEC_TILES) got = cur;
            }
            s_tk = got;
        }
        __syncthreads();
        unsigned tk = s_tk;
        if (tk == 0xFFFFFFFFu) return;
        __syncthreads();

        int mblk = tk / DEC_NBT, nr = tk % DEC_NBT;
        int bm = mblk * 128;
        if (nr < DEC_NB0) {
            gemm_tile<true, true>(smem, hsA, wd0, bd0, nullptr, out, N0, H_, bm, nr * 64);
        } else {
            gemm_tile<true, true>(smem, hsA, wd1, bd1, nullptr, out + (size_t)BT * N0,
                                  N1, H_, bm, (nr - DEC_NB0) * 64);
        }
        __syncthreads();   // all ldsm/STG done before next tile reuses smem
    }
}

// ------------------------- persistent LSTM recurrence (R7 exact) ----------
#define SW_STRIDE 1028
#define SW_WORDS  (32 * SW_STRIDE)
#define SA_STRIDE 36
#define SA_BUF_W  CH_W
#define SA_WARP_W (2 * SA_BUF_W)
#define SA_WORDS  (8 * SA_WARP_W)
#define SRED_STR  34
#define SC_OFF    (SW_WORDS + SA_WORDS)
#define MB_OFF    (SC_OFF + 256)
#define REC_SMEM_BYTES ((MB_OFF + 64) * 4)

__launch_bounds__(256, 1)
__global__ void recurrence_kernel(const float* __restrict__ c0, float* __restrict__ d_out) {
    extern __shared__ uint32_t smem[];
    float* sred = reinterpret_cast<float*>(smem + SW_WORDS);
    float* sc = reinterpret_cast<float*>(smem + SC_OFF);

    const int tid = threadIdx.x;
    const int cta = blockIdx.x;
    const int lane = tid & 31, warp = tid >> 5;
    const uint32_t smem_b = (uint32_t)__cvta_generic_to_shared(smem);
    const int b = tid >> 3, u = tid & 7;

#pragma unroll
    for (int it = 0; it < 32; it++) {
        int lin = tid + it * 256;
        int r = lin >> 8;
        int c4 = lin & 255;
        int gg = r >> 3, rr = r & 7;
        cp16(smem_b + (uint32_t)(r * SW_STRIDE + c4 * 4) * 4,
             g_whh_tf + (size_t)(gg * H_ + cta * 8 + rr) * H_ + c4 * 4);
    }
    asm volatile("cp.async.commit_group;" ::: "memory");
    sc[tid] = c0[(size_t)b * H_ + cta * 8 + u];
    if (tid == 0) {
#pragma unroll
        for (int m = 0; m < 16; m++) mb_init(smem_b + (uint32_t)(MB_OFF + m * 2) * 4, 1);
    }
    asm volatile("cp.async.wait_group 0;" ::: "memory");
    __syncthreads();

    const uint32_t sa_bytes = smem_b + (uint32_t)(SW_WORDS + warp * SA_WARP_W) * 4;
    const uint32_t mb0 = smem_b + (uint32_t)(MB_OFF + warp * 4) * 4;
    const uint32_t mb1 = mb0 + 8;
    unsigned* my_cnt = &g_gcnt[(cta >> 4) * 64];
    const unsigned* wait_cnt = &g_gcnt[warp * 64];
    uint32_t ph0 = 0, ph1 = 0;
    const uint32_t CH_BYTES = CH_W * 4;

    for (int t = 0; t < T_; t++) {
        const uint32_t* hsrc = g_hstf + (size_t)t * HSTEP + (size_t)warp * 4 * CH_W;

        const size_t xb = (size_t)(t * B_ + b) * G_ + (size_t)cta * 8 + u;
        float xp0 = g_xproj[xb];
        float xp1 = g_xproj[xb + H_];
        float xp2 = g_xproj[xb + 2 * H_];
        float xp3 = g_xproj[xb + 3 * H_];

        float acc[2][4][4];
#pragma unroll
        for (int i = 0; i < 2; i++)
#pragma unroll
            for (int j = 0; j < 4; j++)
#pragma unroll
                for (int r = 0; r < 4; r++) acc[i][j][r] = 0.f;

        if (t > 0) {
            if (lane == 0) {
                unsigned need = 16u * (unsigned)t;
                while (ld_acq(wait_cnt) < need) {}
            }
            __syncwarp();
        }

        if (lane == 0) {
            asm volatile("fence.proxy.async.shared::cta;" ::: "memory");
            mb_expect(mb0, CH_BYTES);
            bulkcp(sa_bytes, hsrc, CH_BYTES, mb0);
            mb_expect(mb1, CH_BYTES);
            bulkcp(sa_bytes + SA_BUF_W * 4, hsrc + CH_W, CH_BYTES, mb1);
        }
        __syncwarp();

#pragma unroll
        for (int cc = 0; cc < 4; cc++) {
            if (cc & 1) { mb_wait(mb1, ph1); ph1 ^= 1; }
            else        { mb_wait(mb0, ph0); ph0 ^= 1; }

            const uint32_t abase = sa_bytes + (uint32_t)((cc & 1) * SA_BUF_W) * 4;
            const int colc = cc * 32;
            const int arow = ((lane >> 3) & 1) * 8 + (lane & 7);
            const int ahi = (lane >> 4) * 4;

#pragma unroll
            for (int kp = 0; kp < 2; kp++) {
                uint32_t bfr[4][4];
#pragma unroll
                for (int j = 0; j < 4; j++) {
                    int n = j * 8 + (lane & 7);
                    int col = warp * 128 + colc + kp * 16 + (lane >> 3) * 4;
                    ldsm4(bfr[j][0], bfr[j][1], bfr[j][2], bfr[j][3],
                          smem_b + (uint32_t)(n * SW_STRIDE + col) * 4);
                }
#pragma unroll
                for (int k2 = 0; k2 < 2; k2++) {
                    int kt = kp * 2 + k2;
                    uint32_t afr[2][4];
#pragma unroll
                    for (int i = 0; i < 2; i++) {
                        int row = i * 16 + arow;
                        ldsm4(afr[i][0], afr[i][1], afr[i][2], afr[i][3],
                              abase + (uint32_t)(row * SA_STRIDE + kt * 8 + ahi) * 4);
                    }
#pragma unroll
                    for (int i = 0; i < 2; i++)
#pragma unroll
                        for (int j = 0; j < 4; j++)
                            mma_tf32(acc[i][j][0], acc[i][j][1], acc[i][j][2], acc[i][j][3],
                                     afr[i][0], afr[i][1], afr[i][2], afr[i][3],
                                     bfr[j][k2 * 2], bfr[j][k2 * 2 + 1]);
                }
            }

            if (cc < 2) {
                if (lane == 0) {
                    if (cc & 1) { mb_expect(mb1, CH_BYTES);
                                  bulkcp(abase, hsrc + 3 * CH_W, CH_BYTES, mb1); }
                    else        { mb_expect(mb0, CH_BYTES);
                                  bulkcp(abase, hsrc + 2 * CH_W, CH_BYTES, mb0); }
                }
                __syncwarp();
            }
        }

        __syncwarp();
        const int grp = lane >> 2, tig = lane & 3;
        {
            float* p = sred + warp * SA_WARP_W;
#pragma unroll
            for (int i = 0; i < 2; i++) {
#pragma unroll
                for (int j = 0; j < 4; j++) {
                    int m0 = i * 16 + grp, n0 = j * 8 + tig * 2;
                    *reinterpret_cast<float2*>(p + m0 * SRED_STR + n0) =
                        make_float2(acc[i][j][0], acc[i][j][1]);
                    *reinterpret_cast<float2*>(p + (m0 + 8) * SRED_STR + n0) =
                        make_float2(acc[i][j][2], acc[i][j][3]);
                }
            }
        }
        __syncthreads();

        float s0 = xp0, s1 = xp1, s2 = xp2, s3 = xp3;
#pragma unroll
        for (int w = 0; w < 8; w++) {
            const float* p = sred + w * SA_WARP_W + b * SRED_STR + u;
            s0 += p[0]; s1 += p[8]; s2 += p[16]; s3 += p[24];
        }
        float iv = fsig(s0);
        float fv = fsig(s1);
        float gv = ftanh(s2);
        float ov = fsig(s3);
        float c = fv * sc[tid] + iv * gv;
        sc[tid] = c;
        float h = ov * ftanh(c);

        g_hstf[(size_t)(t + 1) * HSTEP + (size_t)(cta >> 2) * CH_W
               + b * ROWW + (cta & 3) * 8 + u] = f2tf(h);
        if (t == T_ - 1) {
            size_t off_h = (size_t)BT * (N0 + N1);
            d_out[off_h + (size_t)b * H_ + cta * 8 + u] = h;
            d_out[off_h + (size_t)B_ * H_ + (size_t)b * H_ + cta * 8 + u] = c;
        }

        __syncthreads();
        if (tid == 0) red_release(my_cnt, 1u);   // release EVERY step (decoders need t=511)
    }
}

// ------------------------- launch ----------------------------------------
extern "C" void kernel_launch(void* const* d_in, const int* in_sizes, int n_in,
                              void* d_out, int out_size) {
    const int*   tok0 = (const int*)d_in[0];
    const int*   tok1 = (const int*)d_in[1];
    const float* h0   = (const float*)d_in[2];
    const float* c0   = (const float*)d_in[3];
    const float* emb0 = (const float*)d_in[4];
    const float* emb1 = (const float*)d_in[5];
    const float* W_ih = (const float*)d_in[6];
    const float* W_hh = (const float*)d_in[7];
    const float* b_ih = (const float*)d_in[8];
    const float* b_hh = (const float*)d_in[9];
    const float* Wd0  = (const float*)d_in[10];
    const float* bd0  = (const float*)d_in[11];
    const float* Wd1  = (const float*)d_in[12];
    const float* bd1  = (const float*)d_in[13];
    float* out = (float*)d_out;

    static cudaStream_t s2 = nullptr;
    static cudaEvent_t evF = nullptr, evJ = nullptr;
    if (s2 == nullptr) {
        cudaStreamCreateWithFlags(&s2, cudaStreamNonBlocking);
        cudaEventCreateWithFlags(&evF, cudaEventDisableTiming);
        cudaEventCreateWithFlags(&evJ, cudaEventDisableTiming);
        cudaFuncSetAttribute(gemm_xproj_kernel, cudaFuncAttributeMaxDynamicSharedMemorySize, GEMM_SMEM_BYTES);
        cudaFuncSetAttribute(dec_kernel<true>,  cudaFuncAttributeMaxDynamicSharedMemorySize, GEMM_SMEM_BYTES);
        cudaFuncSetAttribute(dec_kernel<false>, cudaFuncAttributeMaxDynamicSharedMemorySize, GEMM_SMEM_BYTES);
        cudaFuncSetAttribute(recurrence_kernel, cudaFuncAttributeMaxDynamicSharedMemorySize, REC_SMEM_BYTES);
    }

    void *px, *pxp, *phs, *pwih, *pwd0, *pwd1;
    cudaGetSymbolAddress(&px, g_x);
    cudaGetSymbolAddress(&pxp, g_xproj);
    cudaGetSymbolAddress(&phs, g_hstf);
    cudaGetSymbolAddress(&pwih, g_wih_tf);
    cudaGetSymbolAddress(&pwd0, g_wd0_tf);
    cudaGetSymbolAddress(&pwd1, g_wd1_tf);

    const uint32_t* hsA = (const uint32_t*)phs + (size_t)HSTEP;   // skip h[-1]

    prep_kernel<<<2048, 256>>>(W_ih, W_hh, Wd0, Wd1, h0);
    pack_kernel<<<BT, 128>>>(tok0, tok1, emb0, emb1);
    gemm_xproj_kernel<<<dim3(G_ / 64, BT / 128), 256, GEMM_SMEM_BYTES>>>(
        (const uint32_t*)px, (const uint32_t*)pwih, b_ih, b_hh, (float*)pxp, G_, E2);

    // fork: persistent decoder fills ALL 20 spare SMs (occ 2 -> 40 CTAs);
    // recurrence CTAs (206KB smem) can never share an SM with workers.
    cudaEventRecord(evF, 0);
    cudaStreamWaitEvent(s2, evF, 0);
    dec_kernel<true><<<40, 256, GEMM_SMEM_BYTES, s2>>>(
        hsA, (const uint32_t*)pwd0, (const uint32_t*)pwd1, bd0, bd1, out);

    recurrence_kernel<<<NCTA, 256, REC_SMEM_BYTES>>>(c0, out);

    // finisher drains the remaining tickets at full chip (148 SMs x occ 2)
    dec_kernel<false><<<296, 256, GEMM_SMEM_BYTES>>>(
        hsA, (const uint32_t*)pwd0, (const uint32_t*)pwd1, bd0, bd1, out);

    cudaEventRecord(evJ, s2);
    cudaStreamWaitEvent(0, evJ, 0);
}

// round 13
// speedup vs baseline: 10.6879x; 10.6879x over previous
#include <cuda_runtime.h>
#include <cstdint>

#define B_   32
#define T_   512
#define E2   512
#define H_   1024
#define G_   4096
#define BT   16384
#define N0   2048
#define N1   512
#define NCTA 128

// chunked h layout: per step, 32 chunks of [32 rows][36 words]
#define ROWW    36
#define CH_W    (32 * ROWW)        // 1152 words per chunk
#define NCH     (H_ / 32)
#define HSTEP   (NCH * CH_W)       // 36864 words per step

// decoder tiles: BM128 x BN128
#define DEC_NB0   (N0 / 128)       // 16
#define DEC_NB1   (N1 / 128)       // 4
#define DEC_NBT   (DEC_NB0 + DEC_NB1)   // 20 n-tiles per m-block
#define DEC_TILES (128 * DEC_NBT)       // 2560

// ------------------------- scratch (device globals, no allocs) -----------
__device__ __align__(256) uint32_t g_x[(size_t)BT * E2];
__device__ __align__(256) float    g_xproj[(size_t)BT * G_];
__device__ __align__(256) uint32_t g_hstf[(size_t)(T_ + 1) * HSTEP];
__device__ __align__(256) uint32_t g_wih_tf[(size_t)G_ * E2];
__device__ __align__(256) uint32_t g_whh_tf[(size_t)G_ * H_];
__device__ __align__(256) uint32_t g_wd0_tf[(size_t)N0 * H_];
__device__ __align__(256) uint32_t g_wd1_tf[(size_t)N1 * H_];
__device__ unsigned g_gcnt[8 * 64];      // 8 group counters, 256B apart
__device__ unsigned g_ticket;            // decoder tile work queue

// ------------------------- helpers ---------------------------------------
__device__ __forceinline__ uint32_t f2tf(float f) {
    uint32_t u;
    asm("cvt.rna.tf32.f32 %0, %1;" : "=r"(u) : "f"(f));
    return u;
}

__device__ __forceinline__ void mma_tf32(float& c0, float& c1, float& c2, float& c3,
                                         uint32_t a0, uint32_t a1, uint32_t a2, uint32_t a3,
                                         uint32_t b0, uint32_t b1) {
    asm volatile(
        "mma.sync.aligned.m16n8k8.row.col.f32.tf32.tf32.f32 "
        "{%0,%1,%2,%3},{%4,%5,%6,%7},{%8,%9},{%0,%1,%2,%3};"
        : "+f"(c0), "+f"(c1), "+f"(c2), "+f"(c3)
        : "r"(a0), "r"(a1), "r"(a2), "r"(a3), "r"(b0), "r"(b1));
}

__device__ __forceinline__ void ldsm4(uint32_t& r0, uint32_t& r1, uint32_t& r2, uint32_t& r3,
                                      uint32_t saddr) {
    asm volatile("ldmatrix.sync.aligned.m8n8.x4.shared.b16 {%0,%1,%2,%3}, [%4];"
                 : "=r"(r0), "=r"(r1), "=r"(r2), "=r"(r3) : "r"(saddr));
}

__device__ __forceinline__ void cp16(uint32_t sdst, const void* gsrc) {
    asm volatile("cp.async.cg.shared.global [%0], [%1], 16;" :: "r"(sdst), "l"(gsrc) : "memory");
}

__device__ __forceinline__ void bulkcp(uint32_t sdst, const void* gsrc, uint32_t bytes,
                                       uint32_t mbar) {
    asm volatile(
        "cp.async.bulk.shared::cta.global.mbarrier::complete_tx::bytes [%0], [%1], %2, [%3];"
        :: "r"(sdst), "l"(gsrc), "r"(bytes), "r"(mbar) : "memory");
}

__device__ __forceinline__ void mb_init(uint32_t mbar, uint32_t cnt) {
    asm volatile("mbarrier.init.shared.b64 [%0], %1;" :: "r"(mbar), "r"(cnt) : "memory");
}

__device__ __forceinline__ void mb_expect(uint32_t mbar, uint32_t bytes) {
    asm volatile("mbarrier.arrive.expect_tx.shared.b64 _, [%0], %1;"
                 :: "r"(mbar), "r"(bytes) : "memory");
}

__device__ __forceinline__ void mb_wait(uint32_t mbar, uint32_t parity) {
    asm volatile(
        "{\n\t.reg .pred P;\n\t"
        "MBW_%=:\n\t"
        "mbarrier.try_wait.parity.acquire.cta.shared::cta.b64 P, [%0], %1, 0x989680;\n\t"
        "@P bra.uni MBD_%=;\n\t"
        "bra.uni MBW_%=;\n\t"
        "MBD_%=:\n\t}"
        :: "r"(mbar), "r"(parity) : "memory");
}

__device__ __forceinline__ unsigned ld_acq(const unsigned* p) {
    unsigned v;
    asm volatile("ld.acquire.gpu.u32 %0, [%1];" : "=r"(v) : "l"(p));
    return v;
}

__device__ __forceinline__ void red_release(unsigned* p, unsigned v) {
    asm volatile("red.release.gpu.global.add.u32 [%0], %1;" :: "l"(p), "r"(v) : "memory");
}

__device__ __forceinline__ float fsig(float x) {
    return __fdividef(1.f, 1.f + __expf(-x));
}
__device__ __forceinline__ float ftanh(float x) {
    return 1.f - __fdividef(2.f, __expf(2.f * x) + 1.f);
}

// ------------------------- prep ------------------------------------------
__global__ void prep_kernel(const float* __restrict__ W_ih, const float* __restrict__ W_hh,
                            const float* __restrict__ Wd0, const float* __restrict__ Wd1,
                            const float* __restrict__ h0) {
    size_t i = (size_t)blockIdx.x * blockDim.x + threadIdx.x;
    size_t stride = (size_t)gridDim.x * blockDim.x;
    for (size_t k = i; k < (size_t)G_ * H_; k += stride) g_whh_tf[k] = f2tf(W_hh[k]);
    for (size_t k = i; k < (size_t)G_ * E2; k += stride) g_wih_tf[k] = f2tf(W_ih[k]);
    for (size_t k = i; k < (size_t)N0 * H_; k += stride) g_wd0_tf[k] = f2tf(Wd0[k]);
    for (size_t k = i; k < (size_t)N1 * H_; k += stride) g_wd1_tf[k] = f2tf(Wd1[k]);
    if (i < (size_t)B_ * H_) {
        int b = (int)(i >> 10), k = (int)(i & 1023);
        g_hstf[(size_t)(k >> 5) * CH_W + b * ROWW + (k & 31)] = f2tf(h0[i]);
    }
    if (i < 8 * 64) g_gcnt[i] = 0;
    if (i == 0) g_ticket = 0;
}

// ------------------------- pack ------------------------------------------
__global__ void pack_kernel(const int* __restrict__ tok0, const int* __restrict__ tok1,
                            const float* __restrict__ emb0, const float* __restrict__ emb1) {
    int row = blockIdx.x;
    int t = row >> 5, b = row & 31;
    int tid = threadIdx.x;
    uint4* dst = reinterpret_cast<uint4*>(g_x + (size_t)row * E2);
    float4 v;
    if (tid < 64) {
        int tk = tok0[b * T_ + t];
        v = reinterpret_cast<const float4*>(emb0 + (size_t)tk * 256)[tid];
    } else {
        int tk = tok1[b * T_ + t];
        v = reinterpret_cast<const float4*>(emb1 + (size_t)tk * 256)[tid - 64];
    }
    dst[tid] = make_uint4(f2tf(v.x), f2tf(v.y), f2tf(v.z), f2tf(v.w));
}

// ------------------------- 256-thr GEMM tile (R7-proven, xproj) ----------
#define GEMM_SMEM_BYTES ((2 * 128 * 36 + 2 * 64 * 36) * 4)   // 55296

__launch_bounds__(256, 2)
__global__ void gemm_xproj_kernel(const uint32_t* __restrict__ A, const uint32_t* __restrict__ Bm,
                                  const float* __restrict__ bias1, const float* __restrict__ bias2,
                                  float* __restrict__ C, int N, int K) {
    extern __shared__ uint32_t smem[];
    uint32_t* sA = smem;
    uint32_t* sB = smem + 2 * 128 * 36;
    const int tid = threadIdx.x;
    const int bn = blockIdx.x * 64;
    const int bm = blockIdx.y * 128;
    const int lane = tid & 31, warp = tid >> 5;
    const int wm = (warp >> 1) * 32;
    const int wn = (warp & 1) * 32;
    const int grp = lane >> 2, tig = lane & 3;
    const int KT = K >> 5;
    const uint32_t smem_b = (uint32_t)__cvta_generic_to_shared(smem);

    uint4 ra[4], rb[2];
    auto gload = [&](int kb) {
#pragma unroll
        for (int i = 0; i < 4; i++) {
            int lin = tid + i * 256;
            int r = lin >> 3, c4 = lin & 7;
            ra[i] = reinterpret_cast<const uint4*>(A + (size_t)(bm + r) * K + kb * 32)[c4];
        }
#pragma unroll
        for (int i = 0; i < 2; i++) {
            int lin = tid + i * 256;
            int r = lin >> 3, c4 = lin & 7;
            rb[i] = reinterpret_cast<const uint4*>(Bm + (size_t)(bn + r) * K + kb * 32)[c4];
        }
    };
    auto sstore = [&](int buf) {
        uint32_t* a = sA + buf * 128 * 36;
        uint32_t* b = sB + buf * 64 * 36;
#pragma unroll
        for (int i = 0; i < 4; i++) {
            int lin = tid + i * 256;
            int r = lin >> 3, c4 = lin & 7;
            *reinterpret_cast<uint4*>(a + r * 36 + c4 * 4) = ra[i];
        }
#pragma unroll
        for (int i = 0; i < 2; i++) {
            int lin = tid + i * 256;
            int r = lin >> 3, c4 = lin & 7;
            *reinterpret_cast<uint4*>(b + r * 36 + c4 * 4) = rb[i];
        }
    };

    float acc[2][4][4];
#pragma unroll
    for (int i = 0; i < 2; i++)
#pragma unroll
        for (int j = 0; j < 4; j++)
#pragma unroll
            for (int r = 0; r < 4; r++) acc[i][j][r] = 0.f;

    gload(0);
    sstore(0);
    __syncthreads();

    const int arow = ((lane >> 3) & 1) * 8 + (lane & 7);
    const int ahi = (lane >> 4) * 4;

    for (int kb = 0; kb < KT; kb++) {
        if (kb + 1 < KT) gload(kb + 1);
        const uint32_t aoff = (uint32_t)((kb & 1) * 128 * 36) * 4;
        const uint32_t boff = (uint32_t)(2 * 128 * 36 + (kb & 1) * 64 * 36) * 4;
#pragma unroll
        for (int kp = 0; kp < 2; kp++) {
            uint32_t bfr[4][4];
#pragma unroll
            for (int j = 0; j < 4; j++) {
                int n = wn + j * 8 + (lane & 7);
                int col = kp * 16 + (lane >> 3) * 4;
                ldsm4(bfr[j][0], bfr[j][1], bfr[j][2], bfr[j][3],
                      smem_b + boff + (uint32_t)(n * 36 + col) * 4);
            }
#pragma unroll
            for (int k2 = 0; k2 < 2; k2++) {
                int kt = kp * 2 + k2;
                uint32_t afr[2][4];
#pragma unroll
                for (int i = 0; i < 2; i++) {
                    int row = wm + i * 16 + arow;
                    ldsm4(afr[i][0], afr[i][1], afr[i][2], afr[i][3],
                          smem_b + aoff + (uint32_t)(row * 36 + kt * 8 + ahi) * 4);
                }
#pragma unroll
                for (int i = 0; i < 2; i++)
#pragma unroll
                    for (int j = 0; j < 4; j++)
                        mma_tf32(acc[i][j][0], acc[i][j][1], acc[i][j][2], acc[i][j][3],
                                 afr[i][0], afr[i][1], afr[i][2], afr[i][3],
                                 bfr[j][k2 * 2], bfr[j][k2 * 2 + 1]);
            }
        }
        if (kb + 1 < KT) {
            __syncthreads();
            sstore((kb + 1) & 1);
            __syncthreads();
        }
    }

#pragma unroll
    for (int i = 0; i < 2; i++) {
#pragma unroll
        for (int j = 0; j < 4; j++) {
            int col = bn + wn + j * 8 + tig * 2;
            float bv0 = bias1[col] + bias2[col];
            float bv1 = bias1[col + 1] + bias2[col + 1];
            int r0 = bm + wm + i * 16 + grp;
            int r1 = r0 + 8;
            *reinterpret_cast<float2*>(C + (size_t)r0 * N + col) =
                make_float2(acc[i][j][0] + bv0, acc[i][j][1] + bv1);
            *reinterpret_cast<float2*>(C + (size_t)r1 * N + col) =
                make_float2(acc[i][j][2] + bv0, acc[i][j][3] + bv1);
        }
    }
}

// ------------------------- 512-thr BM128xBN128 tile (R9-proven body) -----
// 3-stage cp.async pipeline, A from g_hstf chunked layout, REMAP output.
#define GA_ST   (128 * 36)
#define GB_ST   (128 * 36)
#define G_STAGE (GA_ST + GB_ST)            // 9216 words
#define DEC_SMEM_BYTES (3 * G_STAGE * 4)   // 110592

__device__ __forceinline__ void dec_tile_512(
    uint32_t* smem, const uint32_t* __restrict__ A, const uint32_t* __restrict__ Bm,
    const float* __restrict__ bias1, float* __restrict__ C, int N, int bm, int bn) {
    const int tid = threadIdx.x;
    const int lane = tid & 31, warp = tid >> 5;
    const int wm = (warp >> 2) * 32;
    const int wn = (warp & 3) * 32;
    const int grp = lane >> 2, tig = lane & 3;
    const int KT = H_ >> 5;                 // 32
    const uint32_t smem_b = (uint32_t)__cvta_generic_to_shared(smem);

    auto load_stage = [&](int kb, int st) {
        const uint32_t sbase = smem_b + (uint32_t)(st * G_STAGE) * 4;
#pragma unroll
        for (int i = 0; i < 2; i++) {
            int lin = tid + i * 512;
            int r = lin >> 3, c4 = lin & 7;
            int row = bm + r;
            int t = row >> 5, bb = row & 31;
            cp16(sbase + (uint32_t)(r * 36 + c4 * 4) * 4,
                 A + (size_t)t * HSTEP + (size_t)kb * CH_W + bb * ROWW + c4 * 4);
        }
#pragma unroll
        for (int i = 0; i < 2; i++) {
            int lin = tid + i * 512;
            int r = lin >> 3, c4 = lin & 7;
            cp16(sbase + (uint32_t)(GA_ST + r * 36 + c4 * 4) * 4,
                 Bm + (size_t)(bn + r) * H_ + kb * 32 + c4 * 4);
        }
        asm volatile("cp.async.commit_group;" ::: "memory");
    };

    float acc[2][4][4];
#pragma unroll
    for (int i = 0; i < 2; i++)
#pragma unroll
        for (int j = 0; j < 4; j++)
#pragma unroll
            for (int r = 0; r < 4; r++) acc[i][j][r] = 0.f;

    load_stage(0, 0);
    load_stage(1, 1);

    const int arow = ((lane >> 3) & 1) * 8 + (lane & 7);
    const int ahi = (lane >> 4) * 4;

    for (int kb = 0; kb < KT; kb++) {
        if (kb + 1 < KT) { asm volatile("cp.async.wait_group 1;" ::: "memory"); }
        else             { asm volatile("cp.async.wait_group 0;" ::: "memory"); }
        __syncthreads();
        if (kb + 2 < KT) load_stage(kb + 2, (kb + 2) % 3);

        const uint32_t aoff = (uint32_t)((kb % 3) * G_STAGE) * 4;
        const uint32_t boff = aoff + (uint32_t)GA_ST * 4;

#pragma unroll
        for (int kp = 0; kp < 2; kp++) {
            uint32_t bfr[4][4];
#pragma unroll
            for (int j = 0; j < 4; j++) {
                int n = wn + j * 8 + (lane & 7);
                int col = kp * 16 + (lane >> 3) * 4;
                ldsm4(bfr[j][0], bfr[j][1], bfr[j][2], bfr[j][3],
                      smem_b + boff + (uint32_t)(n * 36 + col) * 4);
            }
#pragma unroll
            for (int k2 = 0; k2 < 2; k2++) {
                int kt = kp * 2 + k2;
                uint32_t afr[2][4];
#pragma unroll
                for (int i = 0; i < 2; i++) {
                    int row = wm + i * 16 + arow;
                    ldsm4(afr[i][0], afr[i][1], afr[i][2], afr[i][3],
                          smem_b + aoff + (uint32_t)(row * 36 + kt * 8 + ahi) * 4);
                }
#pragma unroll
                for (int i = 0; i < 2; i++)
#pragma unroll
                    for (int j = 0; j < 4; j++)
                        mma_tf32(acc[i][j][0], acc[i][j][1], acc[i][j][2], acc[i][j][3],
                                 afr[i][0], afr[i][1], afr[i][2], afr[i][3],
                                 bfr[j][k2 * 2], bfr[j][k2 * 2 + 1]);
            }
        }
    }

#pragma unroll
    for (int i = 0; i < 2; i++) {
#pragma unroll
        for (int j = 0; j < 4; j++) {
            int col = bn + wn + j * 8 + tig * 2;
            float bv0 = bias1[col], bv1 = bias1[col + 1];
            int r0 = bm + wm + i * 16 + grp;
            int r1 = r0 + 8;
            int or0 = (r0 & 31) * T_ + (r0 >> 5);
            int or1 = (r1 & 31) * T_ + (r1 >> 5);
            *reinterpret_cast<float2*>(C + (size_t)or0 * N + col) =
                make_float2(acc[i][j][0] + bv0, acc[i][j][1] + bv1);
            *reinterpret_cast<float2*>(C + (size_t)or1 * N + col) =
                make_float2(acc[i][j][2] + bv0, acc[i][j][3] + bv1);
        }
    }
}

// ------------------------- decoder: ticket-queue (512 thr) ----------------
template <bool WAIT>
__launch_bounds__(512, 1)
__global__ void dec_kernel(const uint32_t* __restrict__ hsA,
                           const uint32_t* __restrict__ wd0, const uint32_t* __restrict__ wd1,
                           const float* __restrict__ bd0, const float* __restrict__ bd1,
                           float* __restrict__ out) {
    extern __shared__ uint32_t smem[];
    __shared__ unsigned s_tk;
    const int tid = threadIdx.x;

    for (;;) {
        if (tid == 0) {
            unsigned got = 0xFFFFFFFFu;
            if (WAIT) {
                int idle = 0;
                for (;;) {
                    unsigned cur = *((volatile unsigned*)&g_ticket);
                    if (cur >= DEC_TILES) break;
                    unsigned prog = 0xFFFFFFFFu;
#pragma unroll
                    for (int g = 0; g < 8; g++) prog = umin(prog, ld_acq(&g_gcnt[g * 64]));
                    unsigned avail = (prog >> 6) * DEC_NBT;
                    if (cur < avail) {
                        if (atomicCAS(&g_ticket, cur, cur + 1) == cur) { got = cur; break; }
                        continue;
                    }
                    if (++idle > 3000) break;    // bounded stall: finisher takes the rest
                    __nanosleep(256);
                }
            } else {
                unsigned cur = atomicAdd(&g_ticket, 1u);
                if (cur < DEC_TILES) got = cur;
            }
            s_tk = got;
        }
        __syncthreads();
        unsigned tk = s_tk;
        if (tk == 0xFFFFFFFFu) return;
        __syncthreads();

        int mblk = tk / DEC_NBT, nr = tk % DEC_NBT;
        int bm = mblk * 128;
        if (nr < DEC_NB0) {
            dec_tile_512(smem, hsA, wd0, bd0, out, N0, bm, nr * 128);
        } else {
            dec_tile_512(smem, hsA, wd1, bd1, out + (size_t)BT * N0, N1, bm,
                         (nr - DEC_NB0) * 128);
        }
        __syncthreads();
    }
}

// ------------------------- persistent LSTM recurrence (R7/R11 exact) ------
#define SW_STRIDE 1028
#define SW_WORDS  (32 * SW_STRIDE)
#define SA_STRIDE 36
#define SA_BUF_W  CH_W
#define SA_WARP_W (2 * SA_BUF_W)
#define SA_WORDS  (8 * SA_WARP_W)
#define SRED_STR  34
#define SC_OFF    (SW_WORDS + SA_WORDS)
#define MB_OFF    (SC_OFF + 256)
#define REC_SMEM_BYTES ((MB_OFF + 64) * 4)

__launch_bounds__(256, 1)
__global__ void recurrence_kernel(const float* __restrict__ c0, float* __restrict__ d_out) {
    extern __shared__ uint32_t smem[];
    float* sred = reinterpret_cast<float*>(smem + SW_WORDS);
    float* sc = reinterpret_cast<float*>(smem + SC_OFF);

    const int tid = threadIdx.x;
    const int cta = blockIdx.x;
    const int lane = tid & 31, warp = tid >> 5;
    const uint32_t smem_b = (uint32_t)__cvta_generic_to_shared(smem);
    const int b = tid >> 3, u = tid & 7;

#pragma unroll
    for (int it = 0; it < 32; it++) {
        int lin = tid + it * 256;
        int r = lin >> 8;
        int c4 = lin & 255;
        int gg = r >> 3, rr = r & 7;
        cp16(smem_b + (uint32_t)(r * SW_STRIDE + c4 * 4) * 4,
             g_whh_tf + (size_t)(gg * H_ + cta * 8 + rr) * H_ + c4 * 4);
    }
    asm volatile("cp.async.commit_group;" ::: "memory");
    sc[tid] = c0[(size_t)b * H_ + cta * 8 + u];
    if (tid == 0) {
#pragma unroll
        for (int m = 0; m < 16; m++) mb_init(smem_b + (uint32_t)(MB_OFF + m * 2) * 4, 1);
    }
    asm volatile("cp.async.wait_group 0;" ::: "memory");
    __syncthreads();

    const uint32_t sa_bytes = smem_b + (uint32_t)(SW_WORDS + warp * SA_WARP_W) * 4;
    const uint32_t mb0 = smem_b + (uint32_t)(MB_OFF + warp * 4) * 4;
    const uint32_t mb1 = mb0 + 8;
    unsigned* my_cnt = &g_gcnt[(cta >> 4) * 64];
    const unsigned* wait_cnt = &g_gcnt[warp * 64];
    uint32_t ph0 = 0, ph1 = 0;
    const uint32_t CH_BYTES = CH_W * 4;

    for (int t = 0; t < T_; t++) {
        const uint32_t* hsrc = g_hstf + (size_t)t * HSTEP + (size_t)warp * 4 * CH_W;

        const size_t xb = (size_t)(t * B_ + b) * G_ + (size_t)cta * 8 + u;
        float xp0 = g_xproj[xb];
        float xp1 = g_xproj[xb + H_];
        float xp2 = g_xproj[xb + 2 * H_];
        float xp3 = g_xproj[xb + 3 * H_];

        float acc[2][4][4];
#pragma unroll
        for (int i = 0; i < 2; i++)
#pragma unroll
            for (int j = 0; j < 4; j++)
#pragma unroll
                for (int r = 0; r < 4; r++) acc[i][j][r] = 0.f;

        if (t > 0) {
            if (lane == 0) {
                unsigned need = 16u * (unsigned)t;
                while (ld_acq(wait_cnt) < need) {}
            }
            __syncwarp();
        }

        if (lane == 0) {
            asm volatile("fence.proxy.async.shared::cta;" ::: "memory");
            mb_expect(mb0, CH_BYTES);
            bulkcp(sa_bytes, hsrc, CH_BYTES, mb0);
            mb_expect(mb1, CH_BYTES);
            bulkcp(sa_bytes + SA_BUF_W * 4, hsrc + CH_W, CH_BYTES, mb1);
        }
        __syncwarp();

#pragma unroll
        for (int cc = 0; cc < 4; cc++) {
            if (cc & 1) { mb_wait(mb1, ph1); ph1 ^= 1; }
            else        { mb_wait(mb0, ph0); ph0 ^= 1; }

            const uint32_t abase = sa_bytes + (uint32_t)((cc & 1) * SA_BUF_W) * 4;
            const int colc = cc * 32;
            const int arow = ((lane >> 3) & 1) * 8 + (lane & 7);
            const int ahi = (lane >> 4) * 4;

#pragma unroll
            for (int kp = 0; kp < 2; kp++) {
                uint32_t bfr[4][4];
#pragma unroll
                for (int j = 0; j < 4; j++) {
                    int n = j * 8 + (lane & 7);
                    int col = warp * 128 + colc + kp * 16 + (lane >> 3) * 4;
                    ldsm4(bfr[j][0], bfr[j][1], bfr[j][2], bfr[j][3],
                          smem_b + (uint32_t)(n * SW_STRIDE + col) * 4);
                }
#pragma unroll
                for (int k2 = 0; k2 < 2; k2++) {
                    int kt = kp * 2 + k2;
                    uint32_t afr[2][4];
#pragma unroll
                    for (int i = 0; i < 2; i++) {
                        int row = i * 16 + arow;
                        ldsm4(afr[i][0], afr[i][1], afr[i][2], afr[i][3],
                              abase + (uint32_t)(row * SA_STRIDE + kt * 8 + ahi) * 4);
                    }
#pragma unroll
                    for (int i = 0; i < 2; i++)
#pragma unroll
                        for (int j = 0; j < 4; j++)
                            mma_tf32(acc[i][j][0], acc[i][j][1], acc[i][j][2], acc[i][j][3],
                                     afr[i][0], afr[i][1], afr[i][2], afr[i][3],
                                     bfr[j][k2 * 2], bfr[j][k2 * 2 + 1]);
                }
            }

            if (cc < 2) {
                if (lane == 0) {
                    if (cc & 1) { mb_expect(mb1, CH_BYTES);
                                  bulkcp(abase, hsrc + 3 * CH_W, CH_BYTES, mb1); }
                    else        { mb_expect(mb0, CH_BYTES);
                                  bulkcp(abase, hsrc + 2 * CH_W, CH_BYTES, mb0); }
                }
                __syncwarp();
            }
        }

        __syncwarp();
        const int grp = lane >> 2, tig = lane & 3;
        {
            float* p = sred + warp * SA_WARP_W;
#pragma unroll
            for (int i = 0; i < 2; i++) {
#pragma unroll
                for (int j = 0; j < 4; j++) {
                    int m0 = i * 16 + grp, n0 = j * 8 + tig * 2;
                    *reinterpret_cast<float2*>(p + m0 * SRED_STR + n0) =
                        make_float2(acc[i][j][0], acc[i][j][1]);
                    *reinterpret_cast<float2*>(p + (m0 + 8) * SRED_STR + n0) =
                        make_float2(acc[i][j][2], acc[i][j][3]);
                }
            }
        }
        __syncthreads();

        float s0 = xp0, s1 = xp1, s2 = xp2, s3 = xp3;
#pragma unroll
        for (int w = 0; w < 8; w++) {
            const float* p = sred + w * SA_WARP_W + b * SRED_STR + u;
            s0 += p[0]; s1 += p[8]; s2 += p[16]; s3 += p[24];
        }
        float iv = fsig(s0);
        float fv = fsig(s1);
        float gv = ftanh(s2);
        float ov = fsig(s3);
        float c = fv * sc[tid] + iv * gv;
        sc[tid] = c;
        float h = ov * ftanh(c);

        g_hstf[(size_t)(t + 1) * HSTEP + (size_t)(cta >> 2) * CH_W
               + b * ROWW + (cta & 3) * 8 + u] = f2tf(h);
        if (t == T_ - 1) {
            size_t off_h = (size_t)BT * (N0 + N1);
            d_out[off_h + (size_t)b * H_ + cta * 8 + u] = h;
            d_out[off_h + (size_t)B_ * H_ + (size_t)b * H_ + cta * 8 + u] = c;
        }

        __syncthreads();
        if (tid == 0) red_release(my_cnt, 1u);
    }
}

// ------------------------- launch ----------------------------------------
extern "C" void kernel_launch(void* const* d_in, const int* in_sizes, int n_in,
                              void* d_out, int out_size) {
    const int*   tok0 = (const int*)d_in[0];
    const int*   tok1 = (const int*)d_in[1];
    const float* h0   = (const float*)d_in[2];
    const float* c0   = (const float*)d_in[3];
    const float* emb0 = (const float*)d_in[4];
    const float* emb1 = (const float*)d_in[5];
    const float* W_ih = (const float*)d_in[6];
    const float* W_hh = (const float*)d_in[7];
    const float* b_ih = (const float*)d_in[8];
    const float* b_hh = (const float*)d_in[9];
    const float* Wd0  = (const float*)d_in[10];
    const float* bd0  = (const float*)d_in[11];
    const float* Wd1  = (const float*)d_in[12];
    const float* bd1  = (const float*)d_in[13];
    float* out = (float*)d_out;

    static cudaStream_t s2 = nullptr;
    static cudaEvent_t evF = nullptr, evJ = nullptr;
    if (s2 == nullptr) {
        cudaStreamCreateWithFlags(&s2, cudaStreamNonBlocking);
        cudaEventCreateWithFlags(&evF, cudaEventDisableTiming);
        cudaEventCreateWithFlags(&evJ, cudaEventDisableTiming);
        cudaFuncSetAttribute(gemm_xproj_kernel, cudaFuncAttributeMaxDynamicSharedMemorySize, GEMM_SMEM_BYTES);
        cudaFuncSetAttribute(dec_kernel<true>,  cudaFuncAttributeMaxDynamicSharedMemorySize, DEC_SMEM_BYTES);
        cudaFuncSetAttribute(dec_kernel<false>, cudaFuncAttributeMaxDynamicSharedMemorySize, DEC_SMEM_BYTES);
        cudaFuncSetAttribute(recurrence_kernel, cudaFuncAttributeMaxDynamicSharedMemorySize, REC_SMEM_BYTES);
    }

    void *px, *pxp, *phs, *pwih, *pwd0, *pwd1;
    cudaGetSymbolAddress(&px, g_x);
    cudaGetSymbolAddress(&pxp, g_xproj);
    cudaGetSymbolAddress(&phs, g_hstf);
    cudaGetSymbolAddress(&pwih, g_wih_tf);
    cudaGetSymbolAddress(&pwd0, g_wd0_tf);
    cudaGetSymbolAddress(&pwd1, g_wd1_tf);

    const uint32_t* hsA = (const uint32_t*)phs + (size_t)HSTEP;   // skip h[-1]

    prep_kernel<<<2048, 256>>>(W_ih, W_hh, Wd0, Wd1, h0);
    pack_kernel<<<BT, 128>>>(tok0, tok1, emb0, emb1);
    gemm_xproj_kernel<<<dim3(G_ / 64, BT / 128), 256, GEMM_SMEM_BYTES>>>(
        (const uint32_t*)px, (const uint32_t*)pwih, b_ih, b_hh, (float*)pxp, G_, E2);

    // fork: EXACTLY 20 worker CTAs (placement = 20 distinct SMs; the
    // recurrence's 128 exclusive-SM CTAs need the other 128). 512 thr each.
    cudaEventRecord(evF, 0);
    cudaStreamWaitEvent(s2, evF, 0);
    dec_kernel<true><<<20, 512, DEC_SMEM_BYTES, s2>>>(
        hsA, (const uint32_t*)pwd0, (const uint32_t*)pwd1, bd0, bd1, out);

    recurrence_kernel<<<NCTA, 256, REC_SMEM_BYTES>>>(c0, out);

    // finisher drains remaining tickets chip-wide
    dec_kernel<false><<<148, 512, DEC_SMEM_BYTES>>>(
        hsA, (const uint32_t*)pwd0, (const uint32_t*)pwd1, bd0, bd1, out);

    cudaEventRecord(evJ, s2);
    cudaStreamWaitEvent(0, evJ, 0);
}